// round 9
// baseline (speedup 1.0000x reference)
#include <cuda_runtime.h>
#include <cstdint>

#define NROW 16384

// Scratch (allocation-free: __device__ globals)
__device__ __align__(16) float    g_T1p[8 * 3 * 64 * 768];  // per-t-split B @ Ws^T
__device__ __align__(16) float    g_Cp [4 * 3 * 64 * 64];   // per-s-split T1 @ B^T
__device__ __align__(16) uint32_t g_Df [3 * 16 * 4096];     // D in tf32 frag-image per 64-chunk
__device__ __align__(16) uint32_t g_Af [3 * 16 * 4096];     // A in tf32 frag-image per etile

__device__ __forceinline__ uint32_t f2tf(float f) {
    uint32_t u;
    asm("cvt.rna.tf32.f32 %0, %1;" : "=r"(u) : "f"(f));
    return u;
}

__device__ __forceinline__ uint32_t smem_u32(const void* p) {
    uint32_t a;
    asm("{ .reg .u64 t; cvta.to.shared.u64 t, %1; cvt.u32.u64 %0, t; }" : "=r"(a) : "l"(p));
    return a;
}

__device__ __forceinline__ void mma8(float c[4], const uint32_t a[4], const uint32_t b[2]) {
    asm volatile(
        "mma.sync.aligned.m16n8k8.row.col.f32.tf32.tf32.f32 "
        "{%0,%1,%2,%3},{%4,%5,%6,%7},{%8,%9},{%0,%1,%2,%3};"
        : "+f"(c[0]), "+f"(c[1]), "+f"(c[2]), "+f"(c[3])
        : "r"(a[0]), "r"(a[1]), "r"(a[2]), "r"(a[3]), "r"(b[0]), "r"(b[1]));
}

#define CP_ASYNC16(dst, src) \
    asm volatile("cp.async.cg.shared.global [%0], [%1], 16;" :: "r"(dst), "l"(src) : "memory")
#define CP_COMMIT() asm volatile("cp.async.commit_group;" ::: "memory")
#define CP_WAIT0()  asm volatile("cp.async.wait_group 0;" ::: "memory")

// B-operand frag-image word index for element (n-row nr, k-col kc) in a 64x64 tile
__device__ __forceinline__ int bimg_idx(int nr, int kc) {
    int ct = nr >> 3, gc = nr & 7;
    int ks = kc >> 3, tg = kc & 3, q = (kc >> 2) & 1;
    return ((ct * 8 + ks) * 32 + ((gc * 4 + tg) ^ (ks & 3))) * 2 + q;
}

// ---------------- precompute (atomic-free) ----------------

// T1p[p][k][r][s] = sum_{t in split p} B[k,r,t] * Ws[k,s,t]
__global__ __launch_bounds__(256) void t1_k(const float* __restrict__ B,
                                            const float* __restrict__ Ws) {
    __shared__ float Bs[64][33];
    __shared__ float Wss[128][33];
    int k = blockIdx.z, s0 = blockIdx.x * 128, p = blockIdx.y;
    int t0 = p * 96;
    int tid = threadIdx.x;
    const float* Bk = B  + k * 64 * 768;
    const float* Wk = Ws + k * 768 * 768;

    float acc[4][8];
#pragma unroll
    for (int i = 0; i < 4; i++)
#pragma unroll
        for (int j = 0; j < 8; j++) acc[i][j] = 0.f;

    int rl = tid >> 4;
    int sl = tid & 15;

    for (int tc = 0; tc < 96; tc += 32) {
        int tb = t0 + tc;
        int c4 = (tid & 7) * 4;
#pragma unroll
        for (int pp = 0; pp < 2; pp++) {
            int r = (tid >> 3) + pp * 32;
            float4 v = *(const float4*)(Bk + r * 768 + tb + c4);
            Bs[r][c4] = v.x; Bs[r][c4 + 1] = v.y; Bs[r][c4 + 2] = v.z; Bs[r][c4 + 3] = v.w;
        }
#pragma unroll
        for (int pp = 0; pp < 4; pp++) {
            int s = (tid >> 3) + pp * 32;
            float4 v = *(const float4*)(Wk + (s0 + s) * 768 + tb + c4);
            Wss[s][c4] = v.x; Wss[s][c4 + 1] = v.y; Wss[s][c4 + 2] = v.z; Wss[s][c4 + 3] = v.w;
        }
        __syncthreads();
#pragma unroll 8
        for (int tt = 0; tt < 32; tt++) {
            float bv[4], wv[8];
#pragma unroll
            for (int i = 0; i < 4; i++) bv[i] = Bs[rl + 16 * i][tt];
#pragma unroll
            for (int j = 0; j < 8; j++) wv[j] = Wss[sl + 16 * j][tt];
#pragma unroll
            for (int i = 0; i < 4; i++)
#pragma unroll
                for (int j = 0; j < 8; j++) acc[i][j] += bv[i] * wv[j];
        }
        __syncthreads();
    }
#pragma unroll
    for (int i = 0; i < 4; i++)
#pragma unroll
        for (int j = 0; j < 8; j++)
            g_T1p[((size_t)((p * 3 + k) * 64 + rl + 16 * i)) * 768 + s0 + sl + 16 * j] = acc[i][j];
}

// Cp[sp][k][r][r2] = sum_{s in split sp} (sum_p T1p[p,k,r,s]) * B[k,r2,s]
__global__ __launch_bounds__(256) void c_k(const float* __restrict__ B) {
    __shared__ float T1s[64][33];
    __shared__ float Bs2[64][33];
    int k = blockIdx.y, sp = blockIdx.x;
    int sb0 = sp * 192;
    int tid = threadIdx.x;
    const float* Bk = B + k * 64 * 768;

    float acc[4][4];
#pragma unroll
    for (int i = 0; i < 4; i++)
#pragma unroll
        for (int j = 0; j < 4; j++) acc[i][j] = 0.f;

    int rl  = tid & 15;
    int r2l = tid >> 4;

    for (int sc = 0; sc < 192; sc += 32) {
        int sb = sb0 + sc;
        int c4 = (tid & 7) * 4;
#pragma unroll
        for (int pq = 0; pq < 2; pq++) {
            int r = (tid >> 3) + pq * 32;
            float4 s = make_float4(0.f, 0.f, 0.f, 0.f);
#pragma unroll
            for (int pp = 0; pp < 8; pp++) {
                float4 v = *(const float4*)(g_T1p + ((size_t)((pp * 3 + k) * 64 + r)) * 768 + sb + c4);
                s.x += v.x; s.y += v.y; s.z += v.z; s.w += v.w;
            }
            T1s[r][c4] = s.x; T1s[r][c4 + 1] = s.y; T1s[r][c4 + 2] = s.z; T1s[r][c4 + 3] = s.w;
            float4 w = *(const float4*)(Bk + r * 768 + sb + c4);
            Bs2[r][c4] = w.x; Bs2[r][c4 + 1] = w.y; Bs2[r][c4 + 2] = w.z; Bs2[r][c4 + 3] = w.w;
        }
        __syncthreads();
#pragma unroll 8
        for (int tt = 0; tt < 32; tt++) {
            float tv[4], bv[4];
#pragma unroll
            for (int i = 0; i < 4; i++) tv[i] = T1s[rl + 16 * i][tt];
#pragma unroll
            for (int j = 0; j < 4; j++) bv[j] = Bs2[r2l + 16 * j][tt];
#pragma unroll
            for (int i = 0; i < 4; i++)
#pragma unroll
                for (int j = 0; j < 4; j++) acc[i][j] += tv[i] * bv[j];
        }
        __syncthreads();
    }
#pragma unroll
    for (int i = 0; i < 4; i++)
#pragma unroll
        for (int j = 0; j < 4; j++)
            g_Cp[((sp * 3 + k) * 64 + rl + 16 * i) * 64 + r2l + 16 * j] = acc[i][j];
}

// Combined kernel, grid (192, 3), block 256:
//  blocks x <  128: D[k][d][r] = sum_rp A[k,d,rp]*C[k,rp,r] -> g_Df frag-image
//  blocks x >= 128: gather-build g_Af frag-image from A (4 words / thread, STG.128)
__global__ __launch_bounds__(256) void d_k(const float* __restrict__ A) {
    int k = blockIdx.y;
    if (blockIdx.x >= 128) {
        int xb = blockIdx.x - 128;                    // 0..63
        int widx = xb * 1024 + threadIdx.x * 4;       // word offset within this k
        int et   = widx >> 12;
        int base = widx & 4095;
        const float* Ae = A + (size_t)(k * 1024 + et * 64) * 64;
        int ks = (base >> 6) & 7, ct = base >> 9, sw = ks & 3;
        int L  = (base >> 1) & 31;                    // even
        uint32_t w4[4];
#pragma unroll
        for (int j = 0; j < 4; j++) {
            int lsw = L + (j >> 1);
            int q   = j & 1;
            int g   = lsw ^ sw;
            int nr  = ct * 8 + (g >> 2);
            int kc  = ks * 8 + q * 4 + (g & 3);
            w4[j] = f2tf(Ae[nr * 64 + kc]);
        }
        *(uint4*)&g_Af[((size_t)k * 16 + et) * 4096 + base] =
            make_uint4(w4[0], w4[1], w4[2], w4[3]);
        return;
    }

    __shared__ float Cs[64][66];
    __shared__ float As[8][64];
    int d0 = blockIdx.x * 8;
    int tid = threadIdx.x;
    for (int idx = tid; idx < 4096; idx += 256) {
        float s = 0.f;
#pragma unroll
        for (int sp = 0; sp < 4; sp++) s += g_Cp[(sp * 3 + k) * 4096 + idx];
        Cs[idx >> 6][idx & 63] = s;
    }
    for (int idx = tid; idx < 512; idx += 256)
        As[idx >> 6][idx & 63] = A[(size_t)(k * 1024 + d0 + (idx >> 6)) * 64 + (idx & 63)];
    __syncthreads();
    int dl = tid >> 5, r = (tid & 31) * 2;
    float a0 = 0.f, a1 = 0.f;
#pragma unroll
    for (int rp = 0; rp < 64; rp++) {
        float av = As[dl][rp];
        float2 c = *(const float2*)&Cs[rp][r];
        a0 += av * c.x; a1 += av * c.y;
    }
    int d = d0 + dl;
    uint32_t* img = g_Df + ((size_t)k * 16 + (d >> 6)) * 4096;
    int rr = d & 63;
    img[bimg_idx(r, rr)]     = f2tf(a0);
    img[bimg_idx(r + 1, rr)] = f2tf(a1);
}

// ---------------- fused main GEMM (mma.sync tf32, M=128 tiles, full double-buffer) ----------------
// A-frag smem word order: f = h*2 + q (mma consumes {f0,f2,f1,f3}).
// Dynamic smem 96KB: sA[2] 32KB each (x-frags / u-frags), sB[2] 16KB each (D/A images).
// block 256 (8 warps, 4m x 2n of 32x32 warp tiles), grid (3, 128), 2 blocks/SM.
__global__ __launch_bounds__(256, 2) void fused_k(const float* __restrict__ x,
                                                  float* __restrict__ out) {
    extern __shared__ uint32_t sdyn[];

    const int tid = threadIdx.x;
    const int w = tid >> 5, lane = tid & 31;
    const int gp = lane >> 2, tgp = lane & 3;
    const int kh = blockIdx.x;
    const int r0 = blockIdx.y * 128;
    const int wm = w >> 1, wn = w & 1;
    const int wr = wm * 32, wc = wn * 32;
    const int rt0 = wm * 2;

    const uint32_t* Df = g_Df + (size_t)kh * 16 * 4096;
    const uint32_t* Af = g_Af + (size_t)kh * 16 * 4096;

    // x staging map: each thread owns row set {rowS + p*32} and k-cols [cS, cS+8)
    const int rowS = tid >> 3;              // 0..31
    const int ksS  = tid & 7;               // ks of staged cols
    const int cS   = ksS * 8;
    const int swS  = ksS & 3;
    const int gS   = rowS & 7;
    const int hS   = (rowS >> 3) & 1;

    uint32_t* const sAb[2] = {sdyn, sdyn + 8192};
    uint32_t* const sBb[2] = {sdyn + 16384, sdyn + 20480};
    const uint32_t sBa[2] = {smem_u32(sBb[0]), smem_u32(sBb[1])};

    // prologue: load + stage x chunk 0 into sA[0]; cp.async D chunk 0 -> sB[0]
    float4 xa[8];
#pragma unroll
    for (int p = 0; p < 4; p++) {
        const float* xp = x + (size_t)(r0 + rowS + p * 32) * 1024 + cS;
        xa[2 * p]     = *(const float4*)xp;
        xa[2 * p + 1] = *(const float4*)(xp + 4);
    }
#pragma unroll
    for (int p = 0; p < 4; p++) {
        int rt = 2 * p + (rowS >> 4);
        int basew = ((rt * 8 + ksS) * 32) * 4 + hS * 2;
        float e0[4] = {xa[2 * p].x, xa[2 * p].y, xa[2 * p].z, xa[2 * p].w};
        float e1[4] = {xa[2 * p + 1].x, xa[2 * p + 1].y, xa[2 * p + 1].z, xa[2 * p + 1].w};
#pragma unroll
        for (int j = 0; j < 4; j++) {
            uint32_t addr = smem_u32(&sAb[0][basew + (gS * 4 + (j ^ swS)) * 4]);
            asm volatile("st.shared.v2.b32 [%0], {%1,%2};"
                         :: "r"(addr), "r"(f2tf(e0[j])), "r"(f2tf(e1[j])) : "memory");
        }
    }
#pragma unroll
    for (int p = 0; p < 4; p++)
        CP_ASYNC16(sBa[0] + (tid + p * 256) * 16, Df + (tid + p * 256) * 4);
    CP_COMMIT();

    float acc[2][4][4];
#pragma unroll
    for (int mt = 0; mt < 2; mt++)
#pragma unroll
        for (int nt = 0; nt < 4; nt++)
#pragma unroll
            for (int i = 0; i < 4; i++) acc[mt][nt][i] = 0.f;

    // ---- Phase 1: 16 chunks of 64 depth, ONE sync per chunk ----
    for (int ci = 0; ci < 16; ci++) {
        const int b = ci & 1;
        CP_WAIT0();
        __syncthreads();

        if (ci < 15) {
            const uint32_t* srcD = Df + (size_t)(ci + 1) * 4096;
#pragma unroll
            for (int p = 0; p < 4; p++)
                CP_ASYNC16(sBa[1 - b] + (tid + p * 256) * 16, srcD + (tid + p * 256) * 4);
            CP_COMMIT();
            int kc = (ci + 1) * 64;
#pragma unroll
            for (int p = 0; p < 4; p++) {
                const float* xp = x + (size_t)(r0 + rowS + p * 32) * 1024 + kc + cS;
                xa[2 * p]     = *(const float4*)xp;
                xa[2 * p + 1] = *(const float4*)(xp + 4);
            }
        }

        const uint32_t* Ap = sAb[b];
        const uint32_t* Bp = sBb[b];
#pragma unroll
        for (int ks = 0; ks < 8; ks++) {
            int lsw = lane ^ (ks & 3);
            uint4 T0 = *(const uint4*)&Ap[(((rt0) * 8 + ks) * 32 + lsw) * 4];
            uint4 T1 = *(const uint4*)&Ap[(((rt0 + 1) * 8 + ks) * 32 + lsw) * 4];
            uint32_t a0[4] = {T0.x, T0.z, T0.y, T0.w};
            uint32_t a1[4] = {T1.x, T1.z, T1.y, T1.w};
#pragma unroll
            for (int nt = 0; nt < 4; nt++) {
                uint32_t bb[2];
                *(uint2*)bb = *(const uint2*)&Bp[(((wn * 4 + nt) * 8 + ks) * 32 + lsw) * 2];
                mma8(acc[0][nt], a0, bb);
                mma8(acc[1][nt], a1, bb);
            }
        }

        // stage next x chunk into the other sA buffer (overlaps tensor work)
        if (ci < 15) {
            uint32_t* An = sAb[1 - b];
#pragma unroll
            for (int p = 0; p < 4; p++) {
                int rt = 2 * p + (rowS >> 4);
                int basew = ((rt * 8 + ksS) * 32) * 4 + hS * 2;
                float e0[4] = {xa[2 * p].x, xa[2 * p].y, xa[2 * p].z, xa[2 * p].w};
                float e1[4] = {xa[2 * p + 1].x, xa[2 * p + 1].y, xa[2 * p + 1].z, xa[2 * p + 1].w};
#pragma unroll
                for (int j = 0; j < 4; j++) {
                    uint32_t addr = smem_u32(&An[basew + (gS * 4 + (j ^ swS)) * 4]);
                    asm volatile("st.shared.v2.b32 [%0], {%1,%2};"
                                 :: "r"(addr), "r"(f2tf(e0[j])), "r"(f2tf(e1[j])) : "memory");
                }
            }
        }
    }

    // ---- phase transition: cp.async A etile 0; spill u -> sA[0]; sync; load uf ----
#pragma unroll
    for (int p = 0; p < 4; p++)
        CP_ASYNC16(sBa[0] + (tid + p * 256) * 16, Af + (tid + p * 256) * 4);
    CP_COMMIT();

#pragma unroll
    for (int mt = 0; mt < 2; mt++) {
        int rt = rt0 + mt;
#pragma unroll
        for (int nt = 0; nt < 4; nt++) {
            int ks2 = wn * 4 + nt;
            int sw = ks2 & 3;
#pragma unroll
            for (int i = 0; i < 4; i++) {
                int rcol = 2 * tgp + (i & 1);
                int lane2 = (gp * 4 + (rcol & 3)) ^ sw;
                int f = (i >> 1) * 2 + (rcol >> 2);
                sAb[0][((rt * 8 + ks2) * 32 + lane2) * 4 + f] = f2tf(acc[mt][nt][i]);
            }
        }
    }
    __syncthreads();

    uint32_t uf[2][8][4];
#pragma unroll
    for (int ks = 0; ks < 8; ks++) {
        int lsw = lane ^ (ks & 3);
        uint4 T0 = *(const uint4*)&sAb[0][((rt0 * 8 + ks) * 32 + lsw) * 4];
        uint4 T1 = *(const uint4*)&sAb[0][(((rt0 + 1) * 8 + ks) * 32 + lsw) * 4];
        uf[0][ks][0] = T0.x; uf[0][ks][1] = T0.z; uf[0][ks][2] = T0.y; uf[0][ks][3] = T0.w;
        uf[1][ks][0] = T1.x; uf[1][ks][1] = T1.z; uf[1][ks][2] = T1.y; uf[1][ks][3] = T1.w;
    }

    // ---- Phase 2: 16 etiles of 64, one sync per etile ----
    for (int et = 0; et < 16; et++) {
        const int b = et & 1;
        CP_WAIT0();
        __syncthreads();
        if (et < 15) {
            const uint32_t* srcA = Af + (size_t)(et + 1) * 4096;
#pragma unroll
            for (int p = 0; p < 4; p++)
                CP_ASYNC16(sBa[1 - b] + (tid + p * 256) * 16, srcA + (tid + p * 256) * 4);
            CP_COMMIT();
        }

        float o[2][4][4];
#pragma unroll
        for (int mt = 0; mt < 2; mt++)
#pragma unroll
            for (int nt = 0; nt < 4; nt++)
#pragma unroll
                for (int i = 0; i < 4; i++) o[mt][nt][i] = 0.f;

        const uint32_t* Bp = sBb[b];
#pragma unroll
        for (int ks = 0; ks < 8; ks++) {
            int lsw = lane ^ (ks & 3);
#pragma unroll
            for (int nt = 0; nt < 4; nt++) {
                uint32_t bb[2];
                *(uint2*)bb = *(const uint2*)&Bp[(((wn * 4 + nt) * 8 + ks) * 32 + lsw) * 2];
                mma8(o[0][nt], uf[0][ks], bb);
                mma8(o[1][nt], uf[1][ks], bb);
            }
        }

#pragma unroll
        for (int mt = 0; mt < 2; mt++) {
            int row = r0 + wr + mt * 16 + gp;
#pragma unroll
            for (int nt = 0; nt < 4; nt++) {
                size_t col = (size_t)kh * 1024 + et * 64 + wc + nt * 8 + 2 * tgp;
                *(float2*)(out + (size_t)row * 3072 + col) =
                    make_float2(o[mt][nt][0], o[mt][nt][1]);
                *(float2*)(out + (size_t)(row + 8) * 3072 + col) =
                    make_float2(o[mt][nt][2], o[mt][nt][3]);
            }
        }
    }
}

extern "C" void kernel_launch(void* const* d_in, const int* in_sizes, int n_in,
                              void* d_out, int out_size) {
    (void)in_sizes; (void)n_in; (void)out_size;
    const float* x  = (const float*)d_in[0];
    const float* Ws = (const float*)d_in[1];
    const float* A  = (const float*)d_in[2];
    const float* B  = (const float*)d_in[3];
    float* out = (float*)d_out;

    cudaFuncSetAttribute(fused_k, cudaFuncAttributeMaxDynamicSharedMemorySize, 98304);

    // fused_k is the 4th launch (ncu profiles launch #4)
    t1_k<<<dim3(6, 8, 3), 256>>>(B, Ws);
    c_k<<<dim3(4, 3), 256>>>(B);
    d_k<<<dim3(192, 3), 256>>>(A);
    fused_k<<<dim3(3, 128), 256, 98304>>>(x, out);
}

// round 10
// speedup vs baseline: 1.2161x; 1.2161x over previous
#include <cuda_runtime.h>
#include <cstdint>

#define NROW 16384

// Scratch (allocation-free: __device__ globals)
__device__ __align__(16) float    g_T1p[8 * 3 * 64 * 768];  // per-t-split B @ Ws^T
__device__ __align__(16) float    g_Cp [4 * 3 * 64 * 64];   // per-s-split T1 @ B^T
__device__ __align__(16) uint32_t g_Df [3 * 16 * 4096];     // D in tf32 frag-image per 64-chunk
__device__ __align__(16) uint32_t g_Af [3 * 16 * 4096];     // A in tf32 frag-image per etile

__device__ __forceinline__ uint32_t f2tf(float f) {
    uint32_t u;
    asm("cvt.rna.tf32.f32 %0, %1;" : "=r"(u) : "f"(f));
    return u;
}

__device__ __forceinline__ uint32_t smem_u32(const void* p) {
    uint32_t a;
    asm("{ .reg .u64 t; cvta.to.shared.u64 t, %1; cvt.u32.u64 %0, t; }" : "=r"(a) : "l"(p));
    return a;
}

__device__ __forceinline__ void mma8(float c[4], const uint32_t a[4], const uint32_t b[2]) {
    asm volatile(
        "mma.sync.aligned.m16n8k8.row.col.f32.tf32.tf32.f32 "
        "{%0,%1,%2,%3},{%4,%5,%6,%7},{%8,%9},{%0,%1,%2,%3};"
        : "+f"(c[0]), "+f"(c[1]), "+f"(c[2]), "+f"(c[3])
        : "r"(a[0]), "r"(a[1]), "r"(a[2]), "r"(a[3]), "r"(b[0]), "r"(b[1]));
}

#define CP_ASYNC16(dst, src) \
    asm volatile("cp.async.cg.shared.global [%0], [%1], 16;" :: "r"(dst), "l"(src) : "memory")
#define CP_COMMIT() asm volatile("cp.async.commit_group;" ::: "memory")
#define CP_WAIT0()  asm volatile("cp.async.wait_group 0;" ::: "memory")

// B-operand frag-image word index for element (n-row nr, k-col kc) in a 64x64 tile
__device__ __forceinline__ int bimg_idx(int nr, int kc) {
    int ct = nr >> 3, gc = nr & 7;
    int ks = kc >> 3, tg = kc & 3, q = (kc >> 2) & 1;
    return ((ct * 8 + ks) * 32 + ((gc * 4 + tg) ^ (ks & 3))) * 2 + q;
}

// ---------------- precompute (atomic-free) ----------------

// T1p[p][k][r][s] = sum_{t in split p} B[k,r,t] * Ws[k,s,t]
__global__ __launch_bounds__(256) void t1_k(const float* __restrict__ B,
                                            const float* __restrict__ Ws) {
    __shared__ float Bs[64][33];
    __shared__ float Wss[128][33];
    int k = blockIdx.z, s0 = blockIdx.x * 128, p = blockIdx.y;
    int t0 = p * 96;
    int tid = threadIdx.x;
    const float* Bk = B  + k * 64 * 768;
    const float* Wk = Ws + k * 768 * 768;

    float acc[4][8];
#pragma unroll
    for (int i = 0; i < 4; i++)
#pragma unroll
        for (int j = 0; j < 8; j++) acc[i][j] = 0.f;

    int rl = tid >> 4;
    int sl = tid & 15;

    for (int tc = 0; tc < 96; tc += 32) {
        int tb = t0 + tc;
        int c4 = (tid & 7) * 4;
#pragma unroll
        for (int pp = 0; pp < 2; pp++) {
            int r = (tid >> 3) + pp * 32;
            float4 v = *(const float4*)(Bk + r * 768 + tb + c4);
            Bs[r][c4] = v.x; Bs[r][c4 + 1] = v.y; Bs[r][c4 + 2] = v.z; Bs[r][c4 + 3] = v.w;
        }
#pragma unroll
        for (int pp = 0; pp < 4; pp++) {
            int s = (tid >> 3) + pp * 32;
            float4 v = *(const float4*)(Wk + (s0 + s) * 768 + tb + c4);
            Wss[s][c4] = v.x; Wss[s][c4 + 1] = v.y; Wss[s][c4 + 2] = v.z; Wss[s][c4 + 3] = v.w;
        }
        __syncthreads();
#pragma unroll 8
        for (int tt = 0; tt < 32; tt++) {
            float bv[4], wv[8];
#pragma unroll
            for (int i = 0; i < 4; i++) bv[i] = Bs[rl + 16 * i][tt];
#pragma unroll
            for (int j = 0; j < 8; j++) wv[j] = Wss[sl + 16 * j][tt];
#pragma unroll
            for (int i = 0; i < 4; i++)
#pragma unroll
                for (int j = 0; j < 8; j++) acc[i][j] += bv[i] * wv[j];
        }
        __syncthreads();
    }
#pragma unroll
    for (int i = 0; i < 4; i++)
#pragma unroll
        for (int j = 0; j < 8; j++)
            g_T1p[((size_t)((p * 3 + k) * 64 + rl + 16 * i)) * 768 + s0 + sl + 16 * j] = acc[i][j];
}

// Cp[sp][k][r][r2] = sum_{s in split sp} (sum_p T1p[p,k,r,s]) * B[k,r2,s]
__global__ __launch_bounds__(256) void c_k(const float* __restrict__ B) {
    __shared__ float T1s[64][33];
    __shared__ float Bs2[64][33];
    int k = blockIdx.y, sp = blockIdx.x;
    int sb0 = sp * 192;
    int tid = threadIdx.x;
    const float* Bk = B + k * 64 * 768;

    float acc[4][4];
#pragma unroll
    for (int i = 0; i < 4; i++)
#pragma unroll
        for (int j = 0; j < 4; j++) acc[i][j] = 0.f;

    int rl  = tid & 15;
    int r2l = tid >> 4;

    for (int sc = 0; sc < 192; sc += 32) {
        int sb = sb0 + sc;
        int c4 = (tid & 7) * 4;
#pragma unroll
        for (int pq = 0; pq < 2; pq++) {
            int r = (tid >> 3) + pq * 32;
            float4 s = make_float4(0.f, 0.f, 0.f, 0.f);
#pragma unroll
            for (int pp = 0; pp < 8; pp++) {
                float4 v = *(const float4*)(g_T1p + ((size_t)((pp * 3 + k) * 64 + r)) * 768 + sb + c4);
                s.x += v.x; s.y += v.y; s.z += v.z; s.w += v.w;
            }
            T1s[r][c4] = s.x; T1s[r][c4 + 1] = s.y; T1s[r][c4 + 2] = s.z; T1s[r][c4 + 3] = s.w;
            float4 w = *(const float4*)(Bk + r * 768 + sb + c4);
            Bs2[r][c4] = w.x; Bs2[r][c4 + 1] = w.y; Bs2[r][c4 + 2] = w.z; Bs2[r][c4 + 3] = w.w;
        }
        __syncthreads();
#pragma unroll 8
        for (int tt = 0; tt < 32; tt++) {
            float tv[4], bv[4];
#pragma unroll
            for (int i = 0; i < 4; i++) tv[i] = T1s[rl + 16 * i][tt];
#pragma unroll
            for (int j = 0; j < 4; j++) bv[j] = Bs2[r2l + 16 * j][tt];
#pragma unroll
            for (int i = 0; i < 4; i++)
#pragma unroll
                for (int j = 0; j < 4; j++) acc[i][j] += tv[i] * bv[j];
        }
        __syncthreads();
    }
#pragma unroll
    for (int i = 0; i < 4; i++)
#pragma unroll
        for (int j = 0; j < 4; j++)
            g_Cp[((sp * 3 + k) * 64 + rl + 16 * i) * 64 + r2l + 16 * j] = acc[i][j];
}

// Combined kernel, grid (192, 3), block 256:
//  blocks x <  128: D[k][d][r] = sum_rp A[k,d,rp]*C[k,rp,r] -> g_Df frag-image
//  blocks x >= 128: gather-build g_Af frag-image from A (4 words / thread, STG.128)
__global__ __launch_bounds__(256) void d_k(const float* __restrict__ A) {
    int k = blockIdx.y;
    if (blockIdx.x >= 128) {
        int xb = blockIdx.x - 128;                    // 0..63
        int widx = xb * 1024 + threadIdx.x * 4;       // word offset within this k
        int et   = widx >> 12;
        int base = widx & 4095;
        const float* Ae = A + (size_t)(k * 1024 + et * 64) * 64;
        int ks = (base >> 6) & 7, ct = base >> 9, sw = ks & 3;
        int L  = (base >> 1) & 31;                    // even
        uint32_t w4[4];
#pragma unroll
        for (int j = 0; j < 4; j++) {
            int lsw = L + (j >> 1);
            int q   = j & 1;
            int g   = lsw ^ sw;
            int nr  = ct * 8 + (g >> 2);
            int kc  = ks * 8 + q * 4 + (g & 3);
            w4[j] = f2tf(Ae[nr * 64 + kc]);
        }
        *(uint4*)&g_Af[((size_t)k * 16 + et) * 4096 + base] =
            make_uint4(w4[0], w4[1], w4[2], w4[3]);
        return;
    }

    __shared__ float Cs[64][66];
    __shared__ float As[8][64];
    int d0 = blockIdx.x * 8;
    int tid = threadIdx.x;
    for (int idx = tid; idx < 4096; idx += 256) {
        float s = 0.f;
#pragma unroll
        for (int sp = 0; sp < 4; sp++) s += g_Cp[(sp * 3 + k) * 4096 + idx];
        Cs[idx >> 6][idx & 63] = s;
    }
    for (int idx = tid; idx < 512; idx += 256)
        As[idx >> 6][idx & 63] = A[(size_t)(k * 1024 + d0 + (idx >> 6)) * 64 + (idx & 63)];
    __syncthreads();
    int dl = tid >> 5, r = (tid & 31) * 2;
    float a0 = 0.f, a1 = 0.f;
#pragma unroll
    for (int rp = 0; rp < 64; rp++) {
        float av = As[dl][rp];
        float2 c = *(const float2*)&Cs[rp][r];
        a0 += av * c.x; a1 += av * c.y;
    }
    int d = d0 + dl;
    uint32_t* img = g_Df + ((size_t)k * 16 + (d >> 6)) * 4096;
    int rr = d & 63;
    img[bimg_idx(r, rr)]     = f2tf(a0);
    img[bimg_idx(r + 1, rr)] = f2tf(a1);
}

// ---------------- fused main GEMM (mma.sync tf32, double-buffered sA, 1 sync/chunk) ----------------
// Phase 1: u[64,64] = x_tile @ D(kh). Phase 2: out_tile = u @ A(kh)^T over 16 etiles,
// u-fragments held in registers. block 128 (4 warps, 2x2 of 32x32 warp tiles),
// grid (3, 256); dynamic smem 64KB: sA[2] 16KB each + sB[2] 16KB each.
__global__ __launch_bounds__(128, 3) void fused_k(const float* __restrict__ x,
                                                  float* __restrict__ out) {
    extern __shared__ uint32_t sdyn[];
    uint32_t* const sAb[2] = {sdyn, sdyn + 4096};
    uint32_t* const sBb[2] = {sdyn + 8192, sdyn + 12288};
    const uint32_t sBa[2] = {smem_u32(sBb[0]), smem_u32(sBb[1])};

    const int tid = threadIdx.x;
    const int w = tid >> 5, lane = tid & 31;
    const int gp = lane >> 2, tgp = lane & 3;
    const int kh = blockIdx.x;
    const int r0 = blockIdx.y * 64;
    const int wr = (w >> 1) * 32, wc = (w & 1) * 32;

    const uint32_t* Df = g_Df + (size_t)kh * 16 * 4096;
    const uint32_t* Af = g_Af + (size_t)kh * 16 * 4096;

    const int rowb = tid >> 4;              // 0..7 (g)
    const int c4 = (tid & 15) * 4;
    const int ksX = c4 >> 3, qX = (c4 >> 2) & 1, swX = ksX & 3;

    // prologue: x chunk 0 regs + cp.async D chunk 0 -> sB[0]
    float4 xa[8];
#pragma unroll
    for (int p = 0; p < 8; p++)
        xa[p] = *(const float4*)(x + (size_t)(r0 + rowb + p * 8) * 1024 + c4);
#pragma unroll
    for (int p = 0; p < 8; p++)
        CP_ASYNC16(sBa[0] + (tid + p * 128) * 16, Df + (tid + p * 128) * 4);
    CP_COMMIT();

    float acc[2][4][4];
#pragma unroll
    for (int mt = 0; mt < 2; mt++)
#pragma unroll
        for (int nt = 0; nt < 4; nt++)
#pragma unroll
            for (int i = 0; i < 4; i++) acc[mt][nt][i] = 0.f;

    // ---- Phase 1: 16 chunks of 64 depth, ONE sync per chunk ----
    for (int ci = 0; ci < 16; ci++) {
        const int b = ci & 1;
        uint32_t* const Ab = sAb[b];
        // STS x chunk (tf32, frag-major, paired rows -> STS.64) into sA[b]
#pragma unroll
        for (int rt = 0; rt < 4; rt++) {
            int base = ((rt * 8 + ksX) * 32) * 4 + qX * 2;
            int l0 = rowb * 4;
            float4 v0 = xa[2 * rt], v1 = xa[2 * rt + 1];
            float e0[4] = {v0.x, v0.y, v0.z, v0.w};
            float e1[4] = {v1.x, v1.y, v1.z, v1.w};
#pragma unroll
            for (int j = 0; j < 4; j++) {
                uint32_t addr = smem_u32(&Ab[base + (l0 + (j ^ swX)) * 4]);
                asm volatile("st.shared.v2.b32 [%0], {%1,%2};"
                             :: "r"(addr), "r"(f2tf(e0[j])), "r"(f2tf(e1[j])) : "memory");
            }
        }
        CP_WAIT0();
        __syncthreads();

        // prefetch next chunk: x -> regs, D -> other buffer via cp.async
        if (ci < 15) {
            int kc = (ci + 1) * 64;
#pragma unroll
            for (int p = 0; p < 8; p++)
                xa[p] = *(const float4*)(x + (size_t)(r0 + rowb + p * 8) * 1024 + kc + c4);
            const uint32_t* srcD = Df + (size_t)(ci + 1) * 4096;
#pragma unroll
            for (int p = 0; p < 8; p++)
                CP_ASYNC16(sBa[1 - b] + (tid + p * 128) * 16, srcD + (tid + p * 128) * 4);
            CP_COMMIT();
        }

        const uint32_t* Bp = sBb[b];
#pragma unroll
        for (int ks = 0; ks < 8; ks++) {
            int lsw = lane ^ (ks & 3);
            uint32_t a0[4], a1[4];
            *(uint4*)a0 = *(const uint4*)&Ab[(((2 * (w >> 1)) * 8 + ks) * 32 + lsw) * 4];
            *(uint4*)a1 = *(const uint4*)&Ab[(((2 * (w >> 1) + 1) * 8 + ks) * 32 + lsw) * 4];
#pragma unroll
            for (int nt = 0; nt < 4; nt++) {
                uint32_t bb[2];
                *(uint2*)bb = *(const uint2*)&Bp[((((w & 1) * 4 + nt) * 8 + ks) * 32 + lsw) * 2];
                mma8(acc[0][nt], a0, bb);
                mma8(acc[1][nt], a1, bb);
            }
        }
        // no end-of-chunk sync: sA double-buffered; top-of-chunk sync provides ordering
    }

    // ---- spill u to sA[0] as phase-2 A operand (tf32, frag-major) ----
    // Safe: last readers of sA[0] (chunk 14) completed before the chunk-15 top sync.
#pragma unroll
    for (int mt = 0; mt < 2; mt++) {
        int rt = 2 * (w >> 1) + mt;
#pragma unroll
        for (int nt = 0; nt < 4; nt++) {
            int ks2 = (w & 1) * 4 + nt;
            int sw = ks2 & 3;
#pragma unroll
            for (int i = 0; i < 4; i++) {
                int rcol = 2 * tgp + (i & 1);
                int lane2 = (gp * 4 + (rcol & 3)) ^ sw;
                int f = (rcol >> 2) * 2 + (i >> 1);
                sAb[0][((rt * 8 + ks2) * 32 + lane2) * 4 + f] = f2tf(acc[mt][nt][i]);
            }
        }
    }
    // issue A etile 0 (sB[0]; last read was chunk 14, done before chunk-15 sync)
#pragma unroll
    for (int p = 0; p < 8; p++)
        CP_ASYNC16(sBa[0] + (tid + p * 128) * 16, Af + (tid + p * 128) * 4);
    CP_COMMIT();
    __syncthreads();

    // load u-fragments ONCE into registers (phase-2 A operand)
    uint32_t uf[2][8][4];
#pragma unroll
    for (int ks = 0; ks < 8; ks++) {
        int lsw = lane ^ (ks & 3);
        *(uint4*)uf[0][ks] = *(const uint4*)&sAb[0][(((2 * (w >> 1)) * 8 + ks) * 32 + lsw) * 4];
        *(uint4*)uf[1][ks] = *(const uint4*)&sAb[0][(((2 * (w >> 1) + 1) * 8 + ks) * 32 + lsw) * 4];
    }

    // ---- Phase 2: 16 etiles of 64 ----
    for (int et = 0; et < 16; et++) {
        const int b = et & 1;
        CP_WAIT0();
        __syncthreads();
        if (et < 15) {
            const uint32_t* srcA = Af + (size_t)(et + 1) * 4096;
#pragma unroll
            for (int p = 0; p < 8; p++)
                CP_ASYNC16(sBa[1 - b] + (tid + p * 128) * 16, srcA + (tid + p * 128) * 4);
            CP_COMMIT();
        }

        float o[2][4][4];
#pragma unroll
        for (int mt = 0; mt < 2; mt++)
#pragma unroll
            for (int nt = 0; nt < 4; nt++)
#pragma unroll
                for (int i = 0; i < 4; i++) o[mt][nt][i] = 0.f;

        const uint32_t* Bp = sBb[b];
#pragma unroll
        for (int ks = 0; ks < 8; ks++) {
            int lsw = lane ^ (ks & 3);
#pragma unroll
            for (int nt = 0; nt < 4; nt++) {
                uint32_t bb[2];
                *(uint2*)bb = *(const uint2*)&Bp[((((w & 1) * 4 + nt) * 8 + ks) * 32 + lsw) * 2];
                mma8(o[0][nt], uf[0][ks], bb);
                mma8(o[1][nt], uf[1][ks], bb);
            }
        }

#pragma unroll
        for (int mt = 0; mt < 2; mt++) {
            int row = r0 + wr + mt * 16 + gp;
#pragma unroll
            for (int nt = 0; nt < 4; nt++) {
                size_t col = (size_t)kh * 1024 + et * 64 + wc + nt * 8 + 2 * tgp;
                *(float2*)(out + (size_t)row * 3072 + col) =
                    make_float2(o[mt][nt][0], o[mt][nt][1]);
                *(float2*)(out + (size_t)(row + 8) * 3072 + col) =
                    make_float2(o[mt][nt][2], o[mt][nt][3]);
            }
        }
    }
}

extern "C" void kernel_launch(void* const* d_in, const int* in_sizes, int n_in,
                              void* d_out, int out_size) {
    (void)in_sizes; (void)n_in; (void)out_size;
    const float* x  = (const float*)d_in[0];
    const float* Ws = (const float*)d_in[1];
    const float* A  = (const float*)d_in[2];
    const float* B  = (const float*)d_in[3];
    float* out = (float*)d_out;

    cudaFuncSetAttribute(fused_k, cudaFuncAttributeMaxDynamicSharedMemorySize, 65536);

    // fused_k is the 4th launch (ncu profiles launch #4)
    t1_k<<<dim3(6, 8, 3), 256>>>(B, Ws);
    c_k<<<dim3(4, 3), 256>>>(B);
    d_k<<<dim3(192, 3), 256>>>(A);
    fused_k<<<dim3(3, 256), 128, 65536>>>(x, out);
}

// round 11
// speedup vs baseline: 1.5970x; 1.3133x over previous
#include <cuda_runtime.h>
#include <cuda_fp16.h>
#include <cstdint>

#define NROW 16384

// Scratch (allocation-free: __device__ globals)
__device__ __align__(16) float  g_T1p[8 * 3 * 64 * 768];  // per-t-split B @ Ws^T
__device__ __align__(16) float  g_Cp [4 * 3 * 64 * 64];   // per-s-split T1 @ B^T
__device__ __align__(16) __half g_DfH[3 * 16 * 4096];     // D fp16 B-image per 64-chunk (8KB/tile)
__device__ __align__(16) __half g_AfH[3 * 16 * 4096];     // A fp16 B-image per etile

__device__ __forceinline__ uint32_t smem_u32(const void* p) {
    uint32_t a;
    asm("{ .reg .u64 t; cvta.to.shared.u64 t, %1; cvt.u32.u64 %0, t; }" : "=r"(a) : "l"(p));
    return a;
}

// pack two floats -> f16x2 (lo = first arg)
__device__ __forceinline__ uint32_t pack2h(float lo, float hi) {
    uint32_t r;
    asm("cvt.rn.f16x2.f32 %0, %1, %2;" : "=r"(r) : "f"(hi), "f"(lo));
    return r;
}

// fp16 mma m16n8k16, fp32 accum
__device__ __forceinline__ void mma16(float c[4], const uint32_t a[4], const uint32_t b[2]) {
    asm volatile(
        "mma.sync.aligned.m16n8k16.row.col.f32.f16.f16.f32 "
        "{%0,%1,%2,%3},{%4,%5,%6,%7},{%8,%9},{%0,%1,%2,%3};"
        : "+f"(c[0]), "+f"(c[1]), "+f"(c[2]), "+f"(c[3])
        : "r"(a[0]), "r"(a[1]), "r"(a[2]), "r"(a[3]), "r"(b[0]), "r"(b[1]));
}

#define CP_ASYNC16(dst, src) \
    asm volatile("cp.async.cg.shared.global [%0], [%1], 16;" :: "r"(dst), "l"(src) : "memory")
#define CP_COMMIT() asm volatile("cp.async.commit_group;" ::: "memory")
#define CP_WAIT0()  asm volatile("cp.async.wait_group 0;" ::: "memory")

// A-image lane swizzle: f(ks4) in {0,1,4,5} (touches lane bits 0 and 2)
__device__ __forceinline__ int fsw(int ks4) { return (ks4 & 1) | ((ks4 & 2) << 1); }

// B-image half position for element (n-row nr, k-col kc) in a 64x64 fp16 tile.
// b0 = {B[2tg][n],B[2tg+1][n]}, b1 = {B[2tg+8][n],B[2tg+9][n]} per (lane, ct, ks4).
__device__ __forceinline__ int bhpos(int nr, int kc) {
    int ct = nr >> 3, ln = (nr & 7) * 4 + ((kc & 7) >> 1);
    int ks4 = kc >> 4, q = (kc >> 3) & 1, hb = kc & 1;
    return (ct * 4 + ks4) * 128 + ln * 4 + q * 2 + hb;
}

// ---------------- precompute (atomic-free) ----------------

// T1p[p][k][r][s] = sum_{t in split p} B[k,r,t] * Ws[k,s,t]
__global__ __launch_bounds__(256) void t1_k(const float* __restrict__ B,
                                            const float* __restrict__ Ws) {
    __shared__ float Bs[64][33];
    __shared__ float Wss[128][33];
    int k = blockIdx.z, s0 = blockIdx.x * 128, p = blockIdx.y;
    int t0 = p * 96;
    int tid = threadIdx.x;
    const float* Bk = B  + k * 64 * 768;
    const float* Wk = Ws + k * 768 * 768;

    float acc[4][8];
#pragma unroll
    for (int i = 0; i < 4; i++)
#pragma unroll
        for (int j = 0; j < 8; j++) acc[i][j] = 0.f;

    int rl = tid >> 4;
    int sl = tid & 15;

    for (int tc = 0; tc < 96; tc += 32) {
        int tb = t0 + tc;
        int c4 = (tid & 7) * 4;
#pragma unroll
        for (int pp = 0; pp < 2; pp++) {
            int r = (tid >> 3) + pp * 32;
            float4 v = *(const float4*)(Bk + r * 768 + tb + c4);
            Bs[r][c4] = v.x; Bs[r][c4 + 1] = v.y; Bs[r][c4 + 2] = v.z; Bs[r][c4 + 3] = v.w;
        }
#pragma unroll
        for (int pp = 0; pp < 4; pp++) {
            int s = (tid >> 3) + pp * 32;
            float4 v = *(const float4*)(Wk + (s0 + s) * 768 + tb + c4);
            Wss[s][c4] = v.x; Wss[s][c4 + 1] = v.y; Wss[s][c4 + 2] = v.z; Wss[s][c4 + 3] = v.w;
        }
        __syncthreads();
#pragma unroll 8
        for (int tt = 0; tt < 32; tt++) {
            float bv[4], wv[8];
#pragma unroll
            for (int i = 0; i < 4; i++) bv[i] = Bs[rl + 16 * i][tt];
#pragma unroll
            for (int j = 0; j < 8; j++) wv[j] = Wss[sl + 16 * j][tt];
#pragma unroll
            for (int i = 0; i < 4; i++)
#pragma unroll
                for (int j = 0; j < 8; j++) acc[i][j] += bv[i] * wv[j];
        }
        __syncthreads();
    }
#pragma unroll
    for (int i = 0; i < 4; i++)
#pragma unroll
        for (int j = 0; j < 8; j++)
            g_T1p[((size_t)((p * 3 + k) * 64 + rl + 16 * i)) * 768 + s0 + sl + 16 * j] = acc[i][j];
}

// Cp[sp][k][r][r2] = sum_{s in split sp} (sum_p T1p[p,k,r,s]) * B[k,r2,s]
__global__ __launch_bounds__(256) void c_k(const float* __restrict__ B) {
    __shared__ float T1s[64][33];
    __shared__ float Bs2[64][33];
    int k = blockIdx.y, sp = blockIdx.x;
    int sb0 = sp * 192;
    int tid = threadIdx.x;
    const float* Bk = B + k * 64 * 768;

    float acc[4][4];
#pragma unroll
    for (int i = 0; i < 4; i++)
#pragma unroll
        for (int j = 0; j < 4; j++) acc[i][j] = 0.f;

    int rl  = tid & 15;
    int r2l = tid >> 4;

    for (int sc = 0; sc < 192; sc += 32) {
        int sb = sb0 + sc;
        int c4 = (tid & 7) * 4;
#pragma unroll
        for (int pq = 0; pq < 2; pq++) {
            int r = (tid >> 3) + pq * 32;
            float4 s = make_float4(0.f, 0.f, 0.f, 0.f);
#pragma unroll
            for (int pp = 0; pp < 8; pp++) {
                float4 v = *(const float4*)(g_T1p + ((size_t)((pp * 3 + k) * 64 + r)) * 768 + sb + c4);
                s.x += v.x; s.y += v.y; s.z += v.z; s.w += v.w;
            }
            T1s[r][c4] = s.x; T1s[r][c4 + 1] = s.y; T1s[r][c4 + 2] = s.z; T1s[r][c4 + 3] = s.w;
            float4 w = *(const float4*)(Bk + r * 768 + sb + c4);
            Bs2[r][c4] = w.x; Bs2[r][c4 + 1] = w.y; Bs2[r][c4 + 2] = w.z; Bs2[r][c4 + 3] = w.w;
        }
        __syncthreads();
#pragma unroll 8
        for (int tt = 0; tt < 32; tt++) {
            float tv[4], bv[4];
#pragma unroll
            for (int i = 0; i < 4; i++) tv[i] = T1s[rl + 16 * i][tt];
#pragma unroll
            for (int j = 0; j < 4; j++) bv[j] = Bs2[r2l + 16 * j][tt];
#pragma unroll
            for (int i = 0; i < 4; i++)
#pragma unroll
                for (int j = 0; j < 4; j++) acc[i][j] += tv[i] * bv[j];
        }
        __syncthreads();
    }
#pragma unroll
    for (int i = 0; i < 4; i++)
#pragma unroll
        for (int j = 0; j < 4; j++)
            g_Cp[((sp * 3 + k) * 64 + rl + 16 * i) * 64 + r2l + 16 * j] = acc[i][j];
}

// Combined, grid (160, 3), block 256:
//  x < 128:  D[k][d][r] = sum_rp A[k,d,rp]*C[k,rp,r] -> g_DfH fp16 B-image
//  x >= 128: gather-build g_AfH fp16 B-image from A (16B / thread STG.128)
__global__ __launch_bounds__(256) void d_k(const float* __restrict__ A) {
    int k = blockIdx.y;
    if (blockIdx.x >= 128) {
        int s = (blockIdx.x - 128) * 256 + threadIdx.x;   // 0..8191
        int et = s >> 9;
        int wslot = s & 511;
        int j   = wslot & 15;          // lane pair index
        int ks4 = (wslot >> 4) & 3;
        int ct  = wslot >> 6;          // 0..7
        const float* Ae = A + (size_t)(k * 1024 + et * 64) * 64;
        uint32_t w4[4];
#pragma unroll
        for (int lp = 0; lp < 2; lp++) {
            int ln = 2 * j + lp;
            int nr = ct * 8 + (ln >> 2);
            int kb = ks4 * 16 + (ln & 3) * 2;
#pragma unroll
            for (int q = 0; q < 2; q++) {
                float lo = Ae[nr * 64 + kb + q * 8];
                float hi = Ae[nr * 64 + kb + q * 8 + 1];
                w4[lp * 2 + q] = pack2h(lo, hi);
            }
        }
        // halfpos base = ((ct*4+ks4)*128 + 2j*4) -> word base /2
        int wbase = ((ct * 4 + ks4) * 128 + 2 * j * 4) >> 1;
        *(uint4*)&((uint32_t*)g_AfH)[((size_t)k * 16 + et) * 2048 + wbase] =
            make_uint4(w4[0], w4[1], w4[2], w4[3]);
        return;
    }

    __shared__ float Cs[64][66];
    __shared__ float As[8][64];
    int d0 = blockIdx.x * 8;
    int tid = threadIdx.x;
    for (int idx = tid; idx < 4096; idx += 256) {
        float s = 0.f;
#pragma unroll
        for (int sp = 0; sp < 4; sp++) s += g_Cp[(sp * 3 + k) * 4096 + idx];
        Cs[idx >> 6][idx & 63] = s;
    }
    for (int idx = tid; idx < 512; idx += 256)
        As[idx >> 6][idx & 63] = A[(size_t)(k * 1024 + d0 + (idx >> 6)) * 64 + (idx & 63)];
    __syncthreads();
    int dl = tid >> 5, r = (tid & 31) * 2;
    float a0 = 0.f, a1 = 0.f;
#pragma unroll
    for (int rp = 0; rp < 64; rp++) {
        float av = As[dl][rp];
        float2 c = *(const float2*)&Cs[rp][r];
        a0 += av * c.x; a1 += av * c.y;
    }
    int d = d0 + dl;
    __half* img = g_DfH + ((size_t)k * 16 + (d >> 6)) * 4096;
    int rr = d & 63;                    // k-col of the image
    img[bhpos(r, rr)]     = __float2half(a0);   // n-row = r, n-row = r+1
    img[bhpos(r + 1, rr)] = __float2half(a1);
}

// ---------------- fused main GEMM (fp16 mma m16n8k16, fp32 accum) ----------------
// Phase 1: u[64,64] = x_tile @ D(kh). Phase 2: out = u @ A(kh)^T over 16 etiles,
// u-frags in registers. block 128 (4 warps, 2x2 of 32x32), grid (3, 256), 24KB smem.
__global__ __launch_bounds__(128, 4) void fused_k(const float* __restrict__ x,
                                                  float* __restrict__ out) {
    __shared__ uint32_t sA[4 * 4 * 32 * 4];      // 8KB: x-frags (A-image), then u-frags
    __shared__ uint32_t sB[2][8 * 4 * 32 * 2];   // 2 x 8KB: D / A fp16 B-images

    const int tid = threadIdx.x;
    const int w = tid >> 5, lane = tid & 31;
    const int gp = lane >> 2, tgp = lane & 3;
    const int kh = blockIdx.x;
    const int r0 = blockIdx.y * 64;
    const int wn = w & 1;
    const int wr = (w >> 1) * 32, wc = wn * 32;
    const int rt0 = 2 * (w >> 1);

    const char* Df = (const char*)(g_DfH + (size_t)kh * 16 * 4096);
    const char* Af = (const char*)(g_AfH + (size_t)kh * 16 * 4096);

    // x staging map
    const int rowb = tid >> 4;              // 0..7 = g
    const int m = tid & 15;                 // col group: cols 4m..4m+3
    const int c4 = m * 4;
    const int ks4X = m >> 2, cphiX = (m >> 1) & 1, fX = fsw(ks4X);
    const int tg0 = (m & 1) * 2;            // cp0 = 2m -> tg, cp1 -> tg+1

    const uint32_t sB0 = smem_u32(&sB[0][0]);
    const uint32_t sB1 = smem_u32(&sB[1][0]);

    // prologue
    float4 xa[8];
#pragma unroll
    for (int p = 0; p < 8; p++)
        xa[p] = *(const float4*)(x + (size_t)(r0 + rowb + p * 8) * 1024 + c4);
#pragma unroll
    for (int p = 0; p < 4; p++)
        CP_ASYNC16(sB0 + (tid + p * 128) * 16, Df + (tid + p * 128) * 16);
    CP_COMMIT();

    float acc[2][4][4];
#pragma unroll
    for (int mt = 0; mt < 2; mt++)
#pragma unroll
        for (int nt = 0; nt < 4; nt++)
#pragma unroll
            for (int i = 0; i < 4; i++) acc[mt][nt][i] = 0.f;

    // ---- Phase 1: 16 chunks of 64 depth ----
    for (int ci = 0; ci < 16; ci++) {
        const int b = ci & 1;
        // STS x chunk -> fp16 A-image (8 STS.64 per thread)
#pragma unroll
        for (int rt = 0; rt < 4; rt++) {
            float4 v0 = xa[2 * rt], v1 = xa[2 * rt + 1];
#pragma unroll
            for (int cs = 0; cs < 2; cs++) {
                int tg = tg0 + cs;
                int lane2 = (rowb * 4 + tg) ^ fX;
                int word = ((rt * 4 + ks4X) * 32 + lane2) * 4 + cphiX * 2;
                uint32_t lo = cs ? pack2h(v0.z, v0.w) : pack2h(v0.x, v0.y);
                uint32_t hi = cs ? pack2h(v1.z, v1.w) : pack2h(v1.x, v1.y);
                asm volatile("st.shared.v2.b32 [%0], {%1,%2};"
                             :: "r"(smem_u32(&sA[word])), "r"(lo), "r"(hi) : "memory");
            }
        }
        CP_WAIT0();
        __syncthreads();

        if (ci < 15) {
            int kc = (ci + 1) * 64;
#pragma unroll
            for (int p = 0; p < 8; p++)
                xa[p] = *(const float4*)(x + (size_t)(r0 + rowb + p * 8) * 1024 + kc + c4);
            const char* srcD = Df + (size_t)(ci + 1) * 8192;
            const uint32_t dst = b ? sB0 : sB1;
#pragma unroll
            for (int p = 0; p < 4; p++)
                CP_ASYNC16(dst + (tid + p * 128) * 16, srcD + (tid + p * 128) * 16);
            CP_COMMIT();
        }

        const uint32_t* Bp = sB[b];
#pragma unroll
        for (int ks4 = 0; ks4 < 4; ks4++) {
            int lsw = lane ^ fsw(ks4);
            uint32_t a0[4], a1[4];
            *(uint4*)a0 = *(const uint4*)&sA[((rt0 * 4 + ks4) * 32 + lsw) * 4];
            *(uint4*)a1 = *(const uint4*)&sA[(((rt0 + 1) * 4 + ks4) * 32 + lsw) * 4];
#pragma unroll
            for (int nt = 0; nt < 4; nt++) {
                uint32_t bb[2];
                *(uint2*)bb = *(const uint2*)&Bp[(((wn * 4 + nt) * 4 + ks4) * 32 + lane) * 2];
                mma16(acc[0][nt], a0, bb);
                mma16(acc[1][nt], a1, bb);
            }
        }
        __syncthreads();
    }

    // ---- spill u to sA (fp16 A-image) ----
#pragma unroll
    for (int mt = 0; mt < 2; mt++) {
        int rt = rt0 + mt;
#pragma unroll
        for (int nt = 0; nt < 4; nt++) {
            int ks4u = wn * 2 + (nt >> 1);
            int cphi = nt & 1;
            int lane2 = lane ^ fsw(ks4u);
            int word = ((rt * 4 + ks4u) * 32 + lane2) * 4 + cphi * 2;
            uint32_t lo = pack2h(acc[mt][nt][0], acc[mt][nt][1]);   // row g
            uint32_t hi = pack2h(acc[mt][nt][2], acc[mt][nt][3]);   // row g+8
            asm volatile("st.shared.v2.b32 [%0], {%1,%2};"
                         :: "r"(smem_u32(&sA[word])), "r"(lo), "r"(hi) : "memory");
        }
    }
#pragma unroll
    for (int p = 0; p < 4; p++)
        CP_ASYNC16(sB0 + (tid + p * 128) * 16, Af + (tid + p * 128) * 16);
    CP_COMMIT();
    __syncthreads();

    // u-fragments into registers (32 regs)
    uint32_t uf[2][4][4];
#pragma unroll
    for (int ks4 = 0; ks4 < 4; ks4++) {
        int lsw = lane ^ fsw(ks4);
        *(uint4*)uf[0][ks4] = *(const uint4*)&sA[((rt0 * 4 + ks4) * 32 + lsw) * 4];
        *(uint4*)uf[1][ks4] = *(const uint4*)&sA[(((rt0 + 1) * 4 + ks4) * 32 + lsw) * 4];
    }

    // ---- Phase 2: 16 etiles of 64 ----
    for (int et = 0; et < 16; et++) {
        const int b = et & 1;
        CP_WAIT0();
        __syncthreads();
        if (et < 15) {
            const char* srcA = Af + (size_t)(et + 1) * 8192;
            const uint32_t dst = b ? sB0 : sB1;
#pragma unroll
            for (int p = 0; p < 4; p++)
                CP_ASYNC16(dst + (tid + p * 128) * 16, srcA + (tid + p * 128) * 16);
            CP_COMMIT();
        }

        float o[2][4][4];
#pragma unroll
        for (int mt = 0; mt < 2; mt++)
#pragma unroll
            for (int nt = 0; nt < 4; nt++)
#pragma unroll
                for (int i = 0; i < 4; i++) o[mt][nt][i] = 0.f;

        const uint32_t* Bp = sB[b];
#pragma unroll
        for (int ks4 = 0; ks4 < 4; ks4++) {
#pragma unroll
            for (int nt = 0; nt < 4; nt++) {
                uint32_t bb[2];
                *(uint2*)bb = *(const uint2*)&Bp[(((wn * 4 + nt) * 4 + ks4) * 32 + lane) * 2];
                mma16(o[0][nt], uf[0][ks4], bb);
                mma16(o[1][nt], uf[1][ks4], bb);
            }
        }

#pragma unroll
        for (int mt = 0; mt < 2; mt++) {
            int row = r0 + wr + mt * 16 + gp;
#pragma unroll
            for (int nt = 0; nt < 4; nt++) {
                size_t col = (size_t)kh * 1024 + et * 64 + wc + nt * 8 + 2 * tgp;
                *(float2*)(out + (size_t)row * 3072 + col) =
                    make_float2(o[mt][nt][0], o[mt][nt][1]);
                *(float2*)(out + (size_t)(row + 8) * 3072 + col) =
                    make_float2(o[mt][nt][2], o[mt][nt][3]);
            }
        }
    }
}

extern "C" void kernel_launch(void* const* d_in, const int* in_sizes, int n_in,
                              void* d_out, int out_size) {
    (void)in_sizes; (void)n_in; (void)out_size;
    const float* x  = (const float*)d_in[0];
    const float* Ws = (const float*)d_in[1];
    const float* A  = (const float*)d_in[2];
    const float* B  = (const float*)d_in[3];
    float* out = (float*)d_out;

    // fused_k is the 4th launch (ncu profiles launch #4)
    t1_k<<<dim3(6, 8, 3), 256>>>(B, Ws);
    c_k<<<dim3(4, 3), 256>>>(B);
    d_k<<<dim3(160, 3), 256>>>(A);
    fused_k<<<dim3(3, 256), 128>>>(x, out);
}

// round 12
// speedup vs baseline: 1.7455x; 1.0930x over previous
#include <cuda_runtime.h>
#include <cuda_fp16.h>
#include <cstdint>

#define NROW 16384

// Scratch (allocation-free: __device__ globals)
__device__ __align__(16) float  g_C  [3 * 64 * 64];       // B @ Ws^T @ B^T (atomic-accumulated)
__device__ __align__(16) __half g_DfH[3 * 16 * 4096];     // D fp16 B-image per 64-chunk (8KB/tile)
__device__ __align__(16) __half g_AfH[3 * 16 * 4096];     // A fp16 B-image per etile

__device__ __forceinline__ uint32_t smem_u32(const void* p) {
    uint32_t a;
    asm("{ .reg .u64 t; cvta.to.shared.u64 t, %1; cvt.u32.u64 %0, t; }" : "=r"(a) : "l"(p));
    return a;
}

// pack two floats -> f16x2 (lo = first arg)
__device__ __forceinline__ uint32_t pack2h(float lo, float hi) {
    uint32_t r;
    asm("cvt.rn.f16x2.f32 %0, %1, %2;" : "=r"(r) : "f"(hi), "f"(lo));
    return r;
}

// fp16 mma m16n8k16, fp32 accum
__device__ __forceinline__ void mma16(float c[4], const uint32_t a[4], const uint32_t b[2]) {
    asm volatile(
        "mma.sync.aligned.m16n8k16.row.col.f32.f16.f16.f32 "
        "{%0,%1,%2,%3},{%4,%5,%6,%7},{%8,%9},{%0,%1,%2,%3};"
        : "+f"(c[0]), "+f"(c[1]), "+f"(c[2]), "+f"(c[3])
        : "r"(a[0]), "r"(a[1]), "r"(a[2]), "r"(a[3]), "r"(b[0]), "r"(b[1]));
}

#define CP_ASYNC16(dst, src) \
    asm volatile("cp.async.cg.shared.global [%0], [%1], 16;" :: "r"(dst), "l"(src) : "memory")
#define CP_COMMIT() asm volatile("cp.async.commit_group;" ::: "memory")
#define CP_WAIT0()  asm volatile("cp.async.wait_group 0;" ::: "memory")

// A-image lane swizzle: f(ks4) in {0,1,4,5}
__device__ __forceinline__ int fsw(int ks4) { return (ks4 & 1) | ((ks4 & 2) << 1); }

// B-image half position for element (n-row nr, k-col kc) in a 64x64 fp16 tile
__device__ __forceinline__ int bhpos(int nr, int kc) {
    int ct = nr >> 3, ln = (nr & 7) * 4 + ((kc & 7) >> 1);
    int ks4 = kc >> 4, q = (kc >> 3) & 1, hb = kc & 1;
    return (ct * 4 + ks4) * 128 + ln * 4 + q * 2 + hb;
}

// ---------------- precompute ----------------

__global__ void zero_k() {
    int i = blockIdx.x * blockDim.x + threadIdx.x;
    if (i < 3 * 64 * 64) g_C[i] = 0.f;
}

// Fused T1+C: per (s-split of 128, t-split of 96, k) block:
//   Tloc[r][s] = sum_{t in split} B[k,r,t] * Ws[k,s0+s,t]      (64 x 128)
//   C_part[r][r2] = sum_{s} Tloc[r][s] * B[k,r2,s0+s]          -> atomicAdd g_C
// grid (6, 8, 3), block 256, dynamic smem 69632B.
__global__ __launch_bounds__(256) void t1c_k(const float* __restrict__ B,
                                             const float* __restrict__ Ws) {
    extern __shared__ float sm[];
    float* Tloc = sm;                       // 64 x 133
    float* BsA  = sm + 64 * 133;            // phase A: 64 x 33
    float* WssA = sm + 64 * 133 + 64 * 33;  // phase A: 128 x 33
    float* Btile = sm + 64 * 133;           // phase B: 64 x 133 (overlaps BsA/WssA)

    int k = blockIdx.z, s0 = blockIdx.x * 128, t0 = blockIdx.y * 96;
    int tid = threadIdx.x;
    const float* Bk = B  + k * 64 * 768;
    const float* Wk = Ws + k * 768 * 768;

    float acc[4][8];
#pragma unroll
    for (int i = 0; i < 4; i++)
#pragma unroll
        for (int j = 0; j < 8; j++) acc[i][j] = 0.f;

    int rl = tid >> 4;   // 0..15
    int sl = tid & 15;   // 0..15

    // ---- phase A: local T1 over this t-split ----
    for (int tc = 0; tc < 96; tc += 32) {
        int tb = t0 + tc;
        int c4 = (tid & 7) * 4;
#pragma unroll
        for (int pp = 0; pp < 2; pp++) {
            int r = (tid >> 3) + pp * 32;
            float4 v = *(const float4*)(Bk + r * 768 + tb + c4);
            BsA[r * 33 + c4] = v.x; BsA[r * 33 + c4 + 1] = v.y;
            BsA[r * 33 + c4 + 2] = v.z; BsA[r * 33 + c4 + 3] = v.w;
        }
#pragma unroll
        for (int pp = 0; pp < 4; pp++) {
            int s = (tid >> 3) + pp * 32;
            float4 v = *(const float4*)(Wk + (s0 + s) * 768 + tb + c4);
            WssA[s * 33 + c4] = v.x; WssA[s * 33 + c4 + 1] = v.y;
            WssA[s * 33 + c4 + 2] = v.z; WssA[s * 33 + c4 + 3] = v.w;
        }
        __syncthreads();
#pragma unroll 8
        for (int tt = 0; tt < 32; tt++) {
            float bv[4], wv[8];
#pragma unroll
            for (int i = 0; i < 4; i++) bv[i] = BsA[(rl + 16 * i) * 33 + tt];
#pragma unroll
            for (int j = 0; j < 8; j++) wv[j] = WssA[(sl + 16 * j) * 33 + tt];
#pragma unroll
            for (int i = 0; i < 4; i++)
#pragma unroll
                for (int j = 0; j < 8; j++) acc[i][j] += bv[i] * wv[j];
        }
        __syncthreads();
    }

    // ---- stash Tloc ----
#pragma unroll
    for (int i = 0; i < 4; i++)
#pragma unroll
        for (int j = 0; j < 8; j++)
            Tloc[(rl + 16 * i) * 133 + sl + 16 * j] = acc[i][j];
    __syncthreads();

    // ---- load B tile [64 r2][128 s] ----
    for (int idx = tid; idx < 2048; idx += 256) {
        int row = idx >> 5, c4 = (idx & 31) * 4;
        float4 v = *(const float4*)(Bk + row * 768 + s0 + c4);
        Btile[row * 133 + c4] = v.x; Btile[row * 133 + c4 + 1] = v.y;
        Btile[row * 133 + c4 + 2] = v.z; Btile[row * 133 + c4 + 3] = v.w;
    }
    __syncthreads();

    // ---- phase B: C_part = Tloc @ Btile^T ----
    float c2[4][4];
#pragma unroll
    for (int i = 0; i < 4; i++)
#pragma unroll
        for (int j = 0; j < 4; j++) c2[i][j] = 0.f;

    int rl2  = tid & 15;   // r
    int r2l  = tid >> 4;   // r2
#pragma unroll 4
    for (int s = 0; s < 128; s++) {
        float tv[4], bv[4];
#pragma unroll
        for (int i = 0; i < 4; i++) tv[i] = Tloc[(rl2 + 16 * i) * 133 + s];
#pragma unroll
        for (int j = 0; j < 4; j++) bv[j] = Btile[(r2l + 16 * j) * 133 + s];
#pragma unroll
        for (int i = 0; i < 4; i++)
#pragma unroll
            for (int j = 0; j < 4; j++) c2[i][j] += tv[i] * bv[j];
    }
#pragma unroll
    for (int i = 0; i < 4; i++)
#pragma unroll
        for (int j = 0; j < 4; j++)
            atomicAdd(&g_C[k * 4096 + (rl2 + 16 * i) * 64 + r2l + 16 * j], c2[i][j]);
}

// Combined, grid (160, 3), block 256:
//  x < 128:  D[k][d][r] = sum_rp A[k,d,rp]*C[k,rp,r] -> g_DfH fp16 B-image
//  x >= 128: gather-build g_AfH fp16 B-image from A (16B / thread STG.128)
__global__ __launch_bounds__(256) void d_k(const float* __restrict__ A) {
    int k = blockIdx.y;
    if (blockIdx.x >= 128) {
        int s = (blockIdx.x - 128) * 256 + threadIdx.x;   // 0..8191
        int et = s >> 9;
        int wslot = s & 511;
        int j   = wslot & 15;
        int ks4 = (wslot >> 4) & 3;
        int ct  = wslot >> 6;
        const float* Ae = A + (size_t)(k * 1024 + et * 64) * 64;
        uint32_t w4[4];
#pragma unroll
        for (int lp = 0; lp < 2; lp++) {
            int ln = 2 * j + lp;
            int nr = ct * 8 + (ln >> 2);
            int kb = ks4 * 16 + (ln & 3) * 2;
#pragma unroll
            for (int q = 0; q < 2; q++) {
                float lo = Ae[nr * 64 + kb + q * 8];
                float hi = Ae[nr * 64 + kb + q * 8 + 1];
                w4[lp * 2 + q] = pack2h(lo, hi);
            }
        }
        int wbase = ((ct * 4 + ks4) * 128 + 2 * j * 4) >> 1;
        *(uint4*)&((uint32_t*)g_AfH)[((size_t)k * 16 + et) * 2048 + wbase] =
            make_uint4(w4[0], w4[1], w4[2], w4[3]);
        return;
    }

    __shared__ float Cs[64][66];
    __shared__ float As[8][64];
    int d0 = blockIdx.x * 8;
    int tid = threadIdx.x;
    for (int idx = tid; idx < 4096; idx += 256)
        Cs[idx >> 6][idx & 63] = g_C[k * 4096 + idx];
    for (int idx = tid; idx < 512; idx += 256)
        As[idx >> 6][idx & 63] = A[(size_t)(k * 1024 + d0 + (idx >> 6)) * 64 + (idx & 63)];
    __syncthreads();
    int dl = tid >> 5, r = (tid & 31) * 2;
    float a0 = 0.f, a1 = 0.f;
#pragma unroll
    for (int rp = 0; rp < 64; rp++) {
        float av = As[dl][rp];
        float2 c = *(const float2*)&Cs[rp][r];
        a0 += av * c.x; a1 += av * c.y;
    }
    int d = d0 + dl;
    __half* img = g_DfH + ((size_t)k * 16 + (d >> 6)) * 4096;
    int rr = d & 63;
    img[bhpos(r, rr)]     = __float2half(a0);
    img[bhpos(r + 1, rr)] = __float2half(a1);
}

// ---------------- fused main GEMM (fp16 mma m16n8k16, fp32 accum) ----------------
// Phase 1: u[64,64] = x_tile @ D(kh). Phase 2: out = u @ A(kh)^T over 16 etiles,
// u-frags in registers. block 128 (4 warps, 2x2 of 32x32), grid (3, 256), 24KB smem.
__global__ __launch_bounds__(128, 4) void fused_k(const float* __restrict__ x,
                                                  float* __restrict__ out) {
    __shared__ uint32_t sA[4 * 4 * 32 * 4];      // 8KB: x-frags (A-image), then u-frags
    __shared__ uint32_t sB[2][8 * 4 * 32 * 2];   // 2 x 8KB: D / A fp16 B-images

    const int tid = threadIdx.x;
    const int w = tid >> 5, lane = tid & 31;
    const int gp = lane >> 2, tgp = lane & 3;
    const int kh = blockIdx.x;
    const int r0 = blockIdx.y * 64;
    const int wn = w & 1;
    const int wr = (w >> 1) * 32, wc = wn * 32;
    const int rt0 = 2 * (w >> 1);

    const char* Df = (const char*)(g_DfH + (size_t)kh * 16 * 4096);
    const char* Af = (const char*)(g_AfH + (size_t)kh * 16 * 4096);

    // x staging map
    const int rowb = tid >> 4;              // 0..7 = g
    const int m = tid & 15;                 // col group: cols 4m..4m+3
    const int c4 = m * 4;
    const int ks4X = m >> 2, cphiX = (m >> 1) & 1, fX = fsw(ks4X);
    const int tg0 = (m & 1) * 2;

    const uint32_t sB0 = smem_u32(&sB[0][0]);
    const uint32_t sB1 = smem_u32(&sB[1][0]);

    // prologue (x packed to fp16 at load: 16 regs)
    uint2 xh[8];
#pragma unroll
    for (int p = 0; p < 8; p++) {
        float4 v = *(const float4*)(x + (size_t)(r0 + rowb + p * 8) * 1024 + c4);
        xh[p] = make_uint2(pack2h(v.x, v.y), pack2h(v.z, v.w));
    }
#pragma unroll
    for (int p = 0; p < 4; p++)
        CP_ASYNC16(sB0 + (tid + p * 128) * 16, Df + (tid + p * 128) * 16);
    CP_COMMIT();

    float acc[2][4][4];
#pragma unroll
    for (int mt = 0; mt < 2; mt++)
#pragma unroll
        for (int nt = 0; nt < 4; nt++)
#pragma unroll
            for (int i = 0; i < 4; i++) acc[mt][nt][i] = 0.f;

    // ---- Phase 1: 16 chunks of 64 depth ----
    for (int ci = 0; ci < 16; ci++) {
        const int b = ci & 1;
        // STS x chunk -> fp16 A-image
#pragma unroll
        for (int rt = 0; rt < 4; rt++) {
            uint2 h0 = xh[2 * rt], h1 = xh[2 * rt + 1];
#pragma unroll
            for (int cs = 0; cs < 2; cs++) {
                int tg = tg0 + cs;
                int lane2 = (rowb * 4 + tg) ^ fX;
                int word = ((rt * 4 + ks4X) * 32 + lane2) * 4 + cphiX * 2;
                uint32_t lo = cs ? h0.y : h0.x;
                uint32_t hi = cs ? h1.y : h1.x;
                asm volatile("st.shared.v2.b32 [%0], {%1,%2};"
                             :: "r"(smem_u32(&sA[word])), "r"(lo), "r"(hi) : "memory");
            }
        }
        CP_WAIT0();
        __syncthreads();

        if (ci < 15) {
            int kc = (ci + 1) * 64;
#pragma unroll
            for (int p = 0; p < 8; p++) {
                float4 v = *(const float4*)(x + (size_t)(r0 + rowb + p * 8) * 1024 + kc + c4);
                xh[p] = make_uint2(pack2h(v.x, v.y), pack2h(v.z, v.w));
            }
            const char* srcD = Df + (size_t)(ci + 1) * 8192;
            const uint32_t dst = b ? sB0 : sB1;
#pragma unroll
            for (int p = 0; p < 4; p++)
                CP_ASYNC16(dst + (tid + p * 128) * 16, srcD + (tid + p * 128) * 16);
            CP_COMMIT();
        }

        const uint32_t* Bp = sB[b];
#pragma unroll
        for (int ks4 = 0; ks4 < 4; ks4++) {
            int lsw = lane ^ fsw(ks4);
            uint32_t a0[4], a1[4];
            *(uint4*)a0 = *(const uint4*)&sA[((rt0 * 4 + ks4) * 32 + lsw) * 4];
            *(uint4*)a1 = *(const uint4*)&sA[(((rt0 + 1) * 4 + ks4) * 32 + lsw) * 4];
#pragma unroll
            for (int nt = 0; nt < 4; nt++) {
                uint32_t bb[2];
                *(uint2*)bb = *(const uint2*)&Bp[(((wn * 4 + nt) * 4 + ks4) * 32 + lane) * 2];
                mma16(acc[0][nt], a0, bb);
                mma16(acc[1][nt], a1, bb);
            }
        }
        __syncthreads();
    }

    // ---- spill u to sA (fp16 A-image) ----
#pragma unroll
    for (int mt = 0; mt < 2; mt++) {
        int rt = rt0 + mt;
#pragma unroll
        for (int nt = 0; nt < 4; nt++) {
            int ks4u = wn * 2 + (nt >> 1);
            int cphi = nt & 1;
            int lane2 = lane ^ fsw(ks4u);
            int word = ((rt * 4 + ks4u) * 32 + lane2) * 4 + cphi * 2;
            uint32_t lo = pack2h(acc[mt][nt][0], acc[mt][nt][1]);
            uint32_t hi = pack2h(acc[mt][nt][2], acc[mt][nt][3]);
            asm volatile("st.shared.v2.b32 [%0], {%1,%2};"
                         :: "r"(smem_u32(&sA[word])), "r"(lo), "r"(hi) : "memory");
        }
    }
#pragma unroll
    for (int p = 0; p < 4; p++)
        CP_ASYNC16(sB0 + (tid + p * 128) * 16, Af + (tid + p * 128) * 16);
    CP_COMMIT();
    __syncthreads();

    // u-fragments into registers
    uint32_t uf[2][4][4];
#pragma unroll
    for (int ks4 = 0; ks4 < 4; ks4++) {
        int lsw = lane ^ fsw(ks4);
        *(uint4*)uf[0][ks4] = *(const uint4*)&sA[((rt0 * 4 + ks4) * 32 + lsw) * 4];
        *(uint4*)uf[1][ks4] = *(const uint4*)&sA[(((rt0 + 1) * 4 + ks4) * 32 + lsw) * 4];
    }

    // ---- Phase 2: 16 etiles of 64 ----
    for (int et = 0; et < 16; et++) {
        const int b = et & 1;
        CP_WAIT0();
        __syncthreads();
        if (et < 15) {
            const char* srcA = Af + (size_t)(et + 1) * 8192;
            const uint32_t dst = b ? sB0 : sB1;
#pragma unroll
            for (int p = 0; p < 4; p++)
                CP_ASYNC16(dst + (tid + p * 128) * 16, srcA + (tid + p * 128) * 16);
            CP_COMMIT();
        }

        float o[2][4][4];
#pragma unroll
        for (int mt = 0; mt < 2; mt++)
#pragma unroll
            for (int nt = 0; nt < 4; nt++)
#pragma unroll
                for (int i = 0; i < 4; i++) o[mt][nt][i] = 0.f;

        const uint32_t* Bp = sB[b];
#pragma unroll
        for (int ks4 = 0; ks4 < 4; ks4++) {
#pragma unroll
            for (int nt = 0; nt < 4; nt++) {
                uint32_t bb[2];
                *(uint2*)bb = *(const uint2*)&Bp[(((wn * 4 + nt) * 4 + ks4) * 32 + lane) * 2];
                mma16(o[0][nt], uf[0][ks4], bb);
                mma16(o[1][nt], uf[1][ks4], bb);
            }
        }

#pragma unroll
        for (int mt = 0; mt < 2; mt++) {
            int row = r0 + wr + mt * 16 + gp;
#pragma unroll
            for (int nt = 0; nt < 4; nt++) {
                size_t col = (size_t)kh * 1024 + et * 64 + wc + nt * 8 + 2 * tgp;
                *(float2*)(out + (size_t)row * 3072 + col) =
                    make_float2(o[mt][nt][0], o[mt][nt][1]);
                *(float2*)(out + (size_t)(row + 8) * 3072 + col) =
                    make_float2(o[mt][nt][2], o[mt][nt][3]);
            }
        }
    }
}

extern "C" void kernel_launch(void* const* d_in, const int* in_sizes, int n_in,
                              void* d_out, int out_size) {
    (void)in_sizes; (void)n_in; (void)out_size;
    const float* x  = (const float*)d_in[0];
    const float* Ws = (const float*)d_in[1];
    const float* A  = (const float*)d_in[2];
    const float* B  = (const float*)d_in[3];
    float* out = (float*)d_out;

    cudaFuncSetAttribute(t1c_k, cudaFuncAttributeMaxDynamicSharedMemorySize, 69632);

    // fused_k is the 4th launch (ncu profiles launch #4)
    zero_k<<<48, 256>>>();
    t1c_k<<<dim3(6, 8, 3), 256, 69632>>>(B, Ws);
    d_k<<<dim3(160, 3), 256>>>(A);
    fused_k<<<dim3(3, 256), 128>>>(x, out);
}